// round 4
// baseline (speedup 1.0000x reference)
#include <cuda_runtime.h>
#include <cstdint>

// MessagePassing: out[t] += r[s]*e ; out[s] += r[t]*e  per edge (s,t)
// Inputs: d_in[0]=r [50000,128] f32, d_in[1]=e [500000,128] f32,
//         d_in[2]=a [500000,2] int32. d_out: [50000,128] f32.
//
// Block = 8 warps = 16 consecutive edges. The block's 8KB slab of e is pulled
// into SMEM with one cp.async.bulk (bypasses L1TEX wavefront path); each warp
// then handles 2 edges: e rows from SMEM, r gathers via LDG.128, 4x RED.v4.

#define D_FEAT 128
#define ROW_BYTES 512
#define WARPS_PER_BLOCK 8
#define EDGES_PER_BLOCK (2 * WARPS_PER_BLOCK)          // 16
#define TILE_FLOATS (EDGES_PER_BLOCK * D_FEAT)         // 2048 floats = 8KB

__device__ __forceinline__ void red_add_v4(float* addr, float4 v) {
    asm volatile("red.global.add.v4.f32 [%0], {%1,%2,%3,%4};"
                 :: "l"(addr), "f"(v.x), "f"(v.y), "f"(v.z), "f"(v.w)
                 : "memory");
}

__device__ __forceinline__ float4 mul4(float4 a, float4 b) {
    return make_float4(a.x * b.x, a.y * b.y, a.z * b.z, a.w * b.w);
}

__global__ __launch_bounds__(WARPS_PER_BLOCK * 32)
void mp_bulk_kernel(const float* __restrict__ r,
                    const float* __restrict__ e,
                    const int* __restrict__ a,
                    float* __restrict__ out,
                    int n_edges) {
    __shared__ __align__(16) float smem_e[TILE_FLOATS];
    __shared__ __align__(8) unsigned long long mbar;

    const int base   = blockIdx.x * EDGES_PER_BLOCK;
    const int n_here = min(EDGES_PER_BLOCK, n_edges - base);
    const int tid    = threadIdx.x;

    const uint32_t smem_e_addr = (uint32_t)__cvta_generic_to_shared(smem_e);
    const uint32_t mbar_addr   = (uint32_t)__cvta_generic_to_shared(&mbar);

    if (tid == 0) {
        asm volatile("mbarrier.init.shared.b64 [%0], 1;" :: "r"(mbar_addr) : "memory");
    }
    __syncthreads();

    if (tid == 0) {
        const unsigned bytes = (unsigned)n_here * ROW_BYTES;
        asm volatile("mbarrier.arrive.expect_tx.shared.b64 _, [%0], %1;"
                     :: "r"(mbar_addr), "r"(bytes) : "memory");
        asm volatile("cp.async.bulk.shared::cta.global.mbarrier::complete_tx::bytes "
                     "[%0], [%1], %2, [%3];"
                     :: "r"(smem_e_addr),
                        "l"(e + (long long)base * D_FEAT),
                        "r"(bytes), "r"(mbar_addr)
                     : "memory");
    }

    // Wait for the bulk copy (phase 0; barrier used once per block).
    {
        uint32_t done;
        asm volatile(
            "{\n\t"
            ".reg .pred p;\n\t"
            "mbarrier.try_wait.parity.acquire.cta.shared::cta.b64 p, [%1], 0;\n\t"
            "selp.b32 %0, 1, 0, p;\n\t"
            "}"
            : "=r"(done) : "r"(mbar_addr) : "memory");
        if (!done) {
            asm volatile(
                "{\n\t"
                ".reg .pred P1;\n\t"
                "WAIT_LOOP_%=:\n\t"
                "mbarrier.try_wait.parity.acquire.cta.shared::cta.b64 P1, [%0], 0, 0x989680;\n\t"
                "@P1 bra.uni WAIT_DONE_%=;\n\t"
                "bra.uni WAIT_LOOP_%=;\n\t"
                "WAIT_DONE_%=:\n\t"
                "}"
                :: "r"(mbar_addr) : "memory");
        }
    }

    const int w    = tid >> 5;
    const int lane = tid & 31;
    const int le0  = 2 * w;           // local edge ids
    const int le1  = 2 * w + 1;

    if (base + le0 >= n_edges) return;

    if (base + le1 < n_edges) {
        // common path: both edges valid — one int4 grabs both (s,t) pairs
        int4 st = __ldg(reinterpret_cast<const int4*>(a) + (base >> 1) + w);
        long long s0 = st.x, t0 = st.y, s1 = st.z, t1 = st.w;

        // e rows from SMEM (phased LDS.128, conflict-free)
        float4 ev0 = *reinterpret_cast<const float4*>(&smem_e[le0 * D_FEAT + lane * 4]);
        float4 ev1 = *reinterpret_cast<const float4*>(&smem_e[le1 * D_FEAT + lane * 4]);

        float4 rsv0 = __ldg(reinterpret_cast<const float4*>(r + s0 * D_FEAT) + lane);
        float4 rtv0 = __ldg(reinterpret_cast<const float4*>(r + t0 * D_FEAT) + lane);
        float4 rsv1 = __ldg(reinterpret_cast<const float4*>(r + s1 * D_FEAT) + lane);
        float4 rtv1 = __ldg(reinterpret_cast<const float4*>(r + t1 * D_FEAT) + lane);

        red_add_v4(out + t0 * D_FEAT + lane * 4, mul4(rsv0, ev0));
        red_add_v4(out + s0 * D_FEAT + lane * 4, mul4(rtv0, ev0));
        red_add_v4(out + t1 * D_FEAT + lane * 4, mul4(rsv1, ev1));
        red_add_v4(out + s1 * D_FEAT + lane * 4, mul4(rtv1, ev1));
    } else {
        // tail: single edge
        int2 st = __ldg(reinterpret_cast<const int2*>(a) + base + le0);
        long long s0 = st.x, t0 = st.y;
        float4 ev0  = *reinterpret_cast<const float4*>(&smem_e[le0 * D_FEAT + lane * 4]);
        float4 rsv0 = __ldg(reinterpret_cast<const float4*>(r + s0 * D_FEAT) + lane);
        float4 rtv0 = __ldg(reinterpret_cast<const float4*>(r + t0 * D_FEAT) + lane);
        red_add_v4(out + t0 * D_FEAT + lane * 4, mul4(rsv0, ev0));
        red_add_v4(out + s0 * D_FEAT + lane * 4, mul4(rtv0, ev0));
    }
}

extern "C" void kernel_launch(void* const* d_in, const int* in_sizes, int n_in,
                              void* d_out, int out_size) {
    const float* r = (const float*)d_in[0];
    const float* e = (const float*)d_in[1];
    const int*   a = (const int*)d_in[2];
    float*     out = (float*)d_out;

    int n_edges = in_sizes[1] / D_FEAT;   // 500000

    cudaMemsetAsync(d_out, 0, (size_t)out_size * sizeof(float), 0);

    int blocks = (n_edges + EDGES_PER_BLOCK - 1) / EDGES_PER_BLOCK;   // 31250
    mp_bulk_kernel<<<blocks, WARPS_PER_BLOCK * 32>>>(r, e, a, out, n_edges);
}

// round 6
// speedup vs baseline: 1.0109x; 1.0109x over previous
#include <cuda_runtime.h>
#include <cstdint>

// MessagePassing: out[t] += r[s]*e ; out[s] += r[t]*e  per edge (s,t)
// Inputs: d_in[0]=r [50000,128] f32, d_in[1]=e [500000,128] f32,
//         d_in[2]=a [500000,2] int32. d_out: [50000,128] f32.
//
// Warp = 2 edges. Each 512B row access is issued as 4 independent scalar
// 128B-coalesced instructions (lane covers cols lane+32k) so every L1TEX
// wavefront comes from its own instruction (1.0 cyc/wf cross-instruction rate
// instead of 2.07 cyc/wf within-LDG replay rate).
//
// (Resubmission of R5 — previous round died to a broker/container infra
// failure before producing any measurement.)

#define D_FEAT 128
#define WARPS_PER_BLOCK 8

__device__ __forceinline__ void red_add_f32(float* addr, float v) {
    asm volatile("red.global.add.f32 [%0], %1;" :: "l"(addr), "f"(v) : "memory");
}

__global__ __launch_bounds__(WARPS_PER_BLOCK * 32)
void mp_scalar_kernel(const float* __restrict__ r,
                      const float* __restrict__ e,
                      const int* __restrict__ a,
                      float* __restrict__ out,
                      int n_edges) {
    const int pair = blockIdx.x * WARPS_PER_BLOCK + (threadIdx.x >> 5);
    const int lane = threadIdx.x & 31;
    const int e0   = 2 * pair;
    if (e0 >= n_edges) return;

    float ev0[4], ev1[4], rsv0[4], rtv0[4], rsv1[4], rtv1[4];

    if (e0 + 1 < n_edges) {
        int4 st = __ldg(reinterpret_cast<const int4*>(a) + pair);
        const long long s0 = st.x, t0 = st.y, s1 = st.z, t1 = st.w;

        const float* ep0 = e + (long long)e0 * D_FEAT + lane;
        const float* ep1 = ep0 + D_FEAT;
        const float* rs0 = r + s0 * D_FEAT + lane;
        const float* rt0 = r + t0 * D_FEAT + lane;
        const float* rs1 = r + s1 * D_FEAT + lane;
        const float* rt1 = r + t1 * D_FEAT + lane;

        // 24 independent coalesced 128B loads in flight
        #pragma unroll
        for (int k = 0; k < 4; k++) ev0[k]  = __ldcs(ep0 + 32 * k);
        #pragma unroll
        for (int k = 0; k < 4; k++) ev1[k]  = __ldcs(ep1 + 32 * k);
        #pragma unroll
        for (int k = 0; k < 4; k++) rsv0[k] = __ldg(rs0 + 32 * k);
        #pragma unroll
        for (int k = 0; k < 4; k++) rtv0[k] = __ldg(rt0 + 32 * k);
        #pragma unroll
        for (int k = 0; k < 4; k++) rsv1[k] = __ldg(rs1 + 32 * k);
        #pragma unroll
        for (int k = 0; k < 4; k++) rtv1[k] = __ldg(rt1 + 32 * k);

        float* ot0 = out + t0 * D_FEAT + lane;
        float* os0 = out + s0 * D_FEAT + lane;
        float* ot1 = out + t1 * D_FEAT + lane;
        float* os1 = out + s1 * D_FEAT + lane;

        #pragma unroll
        for (int k = 0; k < 4; k++) red_add_f32(ot0 + 32 * k, rsv0[k] * ev0[k]);
        #pragma unroll
        for (int k = 0; k < 4; k++) red_add_f32(os0 + 32 * k, rtv0[k] * ev0[k]);
        #pragma unroll
        for (int k = 0; k < 4; k++) red_add_f32(ot1 + 32 * k, rsv1[k] * ev1[k]);
        #pragma unroll
        for (int k = 0; k < 4; k++) red_add_f32(os1 + 32 * k, rtv1[k] * ev1[k]);
    } else {
        // tail: single edge
        int2 st = __ldg(reinterpret_cast<const int2*>(a) + e0);
        const long long s0 = st.x, t0 = st.y;
        const float* ep0 = e + (long long)e0 * D_FEAT + lane;
        const float* rs0 = r + s0 * D_FEAT + lane;
        const float* rt0 = r + t0 * D_FEAT + lane;
        #pragma unroll
        for (int k = 0; k < 4; k++) ev0[k]  = __ldcs(ep0 + 32 * k);
        #pragma unroll
        for (int k = 0; k < 4; k++) rsv0[k] = __ldg(rs0 + 32 * k);
        #pragma unroll
        for (int k = 0; k < 4; k++) rtv0[k] = __ldg(rt0 + 32 * k);
        float* ot0 = out + t0 * D_FEAT + lane;
        float* os0 = out + s0 * D_FEAT + lane;
        #pragma unroll
        for (int k = 0; k < 4; k++) red_add_f32(ot0 + 32 * k, rsv0[k] * ev0[k]);
        #pragma unroll
        for (int k = 0; k < 4; k++) red_add_f32(os0 + 32 * k, rtv0[k] * ev0[k]);
    }
}

extern "C" void kernel_launch(void* const* d_in, const int* in_sizes, int n_in,
                              void* d_out, int out_size) {
    const float* r = (const float*)d_in[0];
    const float* e = (const float*)d_in[1];
    const int*   a = (const int*)d_in[2];
    float*     out = (float*)d_out;

    int n_edges = in_sizes[1] / D_FEAT;   // 500000
    int n_pairs = (n_edges + 1) >> 1;     // 250000

    cudaMemsetAsync(d_out, 0, (size_t)out_size * sizeof(float), 0);

    int blocks = (n_pairs + WARPS_PER_BLOCK - 1) / WARPS_PER_BLOCK;
    mp_scalar_kernel<<<blocks, WARPS_PER_BLOCK * 32>>>(r, e, a, out, n_edges);
}